// round 15
// baseline (speedup 1.0000x reference)
#include <cuda_runtime.h>
#include <cuda_bf16.h>
#include <cstdint>
#include <math.h>

#define NL    4
#define DMODEL 512
#define NH    8
#define DHEAD 64
#define DFF_  1024
#define SEQ   2048
#define BATCH 2
#define NROWS (BATCH*SEQ)          // 4096
#define OUTX  ((size_t)NROWS*DMODEL)  // 2097152
#define QKSZ  ((size_t)NROWS*DMODEL)  // 2M elements
#define NRELS 4095

#define DDc   ((size_t)DMODEL*DMODEL)  // 262144
#define DFc   ((size_t)DMODEL*DFF_)    // 524288
#define WARENA (16*DDc + 12*DFc)

typedef unsigned long long u64;

// ---------------- scratch ----------------
__device__ float g_x [NROWS*DMODEL];
__device__ float g_f0[NROWS*DFF_];      // reused as bf16 hi for geglu output
__device__ float g_f1[NROWS*DFF_];      // reused as bf16 lo
__device__ float g_btab[NH*NRELS];      // per-head rel-bias table
__device__ __nv_bfloat16 g_ah[NROWS*DFF_];
__device__ __nv_bfloat16 g_al[NROWS*DFF_];
__device__ __nv_bfloat16 g_oh[NROWS*DMODEL];
__device__ __nv_bfloat16 g_ol[NROWS*DMODEL];
__device__ __nv_bfloat16 g_vh[NROWS*DMODEL];    // V split, [row, 512] layout
__device__ __nv_bfloat16 g_vl[NROWS*DMODEL];
__device__ __nv_bfloat16 g_wh[WARENA];
__device__ __nv_bfloat16 g_wl[WARENA];

// ---------------- helpers ----------------
__device__ __forceinline__ uint32_t smem_u32(const void* p) {
    uint32_t a;
    asm("{ .reg .u64 t; cvta.to.shared.u64 t, %1; cvt.u32.u64 %0, t; }" : "=r"(a) : "l"(p));
    return a;
}
#define CP_ASYNC16(sa, ga) \
    asm volatile("cp.async.cg.shared.global [%0], [%1], 16;" :: "r"(sa), "l"(ga))
#define CP_COMMIT() asm volatile("cp.async.commit_group;" ::: "memory")
template <int N>
__device__ __forceinline__ void cp_wait() {
    asm volatile("cp.async.wait_group %0;" :: "n"(N) : "memory");
}
__device__ __forceinline__ void ldmx4(uint32_t* r, uint32_t addr) {
    asm volatile("ldmatrix.sync.aligned.m8n8.x4.shared.b16 {%0,%1,%2,%3}, [%4];"
                 : "=r"(r[0]), "=r"(r[1]), "=r"(r[2]), "=r"(r[3]) : "r"(addr));
}
__device__ __forceinline__ void ldmx4t(uint32_t* r, uint32_t addr) {
    asm volatile("ldmatrix.sync.aligned.m8n8.x4.trans.shared.b16 {%0,%1,%2,%3}, [%4];"
                 : "=r"(r[0]), "=r"(r[1]), "=r"(r[2]), "=r"(r[3]) : "r"(addr));
}
__device__ __forceinline__ void mma16816(float* d, const uint32_t* a,
                                         uint32_t b0, uint32_t b1) {
    asm volatile(
        "mma.sync.aligned.m16n8k16.row.col.f32.bf16.bf16.f32 "
        "{%0,%1,%2,%3}, {%4,%5,%6,%7}, {%8,%9}, {%0,%1,%2,%3};"
        : "+f"(d[0]), "+f"(d[1]), "+f"(d[2]), "+f"(d[3])
        : "r"(a[0]), "r"(a[1]), "r"(a[2]), "r"(a[3]), "r"(b0), "r"(b1));
}
__device__ __forceinline__ uint32_t pack_bf(__nv_bfloat16 a, __nv_bfloat16 b) {
    __nv_bfloat162 p(a, b);
    return *reinterpret_cast<uint32_t*>(&p);
}
__device__ __forceinline__ void split_bf16(float v, __nv_bfloat16& h, __nv_bfloat16& l) {
    h = __float2bfloat16(v);
    l = __float2bfloat16(v - __bfloat162float(h));
}
__device__ __forceinline__ void split_store2(float a, float b,
                                             __nv_bfloat16* hi, __nv_bfloat16* lo) {
    __nv_bfloat16 h0, h1, l0, l1;
    split_bf16(a, h0, l0);
    split_bf16(b, h1, l1);
    *reinterpret_cast<uint32_t*>(hi) = pack_bf(h0, h1);
    *reinterpret_cast<uint32_t*>(lo) = pack_bf(l0, l1);
}
__device__ __forceinline__ float gelu_new(float xx) {
    float inner = 0.7978845608028654f * (xx + 0.044715f * (xx * xx * xx));
    return 0.5f * xx * (1.0f + tanhf(inner));
}

// ---------------- small kernels ----------------
__global__ __launch_bounds__(256) void embed_k(const int* __restrict__ ids,
                                               const float* __restrict__ emb,
                                               float* __restrict__ x) {
    const int row = blockIdx.x;
    const size_t src = (size_t)ids[row] * DMODEL;
    const size_t dst = (size_t)row * DMODEL;
    for (int i = threadIdx.x; i < DMODEL; i += 256) x[dst + i] = emb[src + i];
}

__global__ __launch_bounds__(256) void bias_tab_k(const float* __restrict__ rb,
                                                  float* __restrict__ btab) {
    int idx = blockIdx.x * 256 + threadIdx.x;
    if (idx >= NH * NRELS) return;
    int hh = idx / NRELS;
    int rel = (idx % NRELS) - 2047;
    int bucket = (rel > 0) ? 16 : 0;
    int rp = (rel < 0) ? -rel : rel;
    int add;
    if (rp < 8) {
        add = rp;
    } else {
        float t = logf((float)rp / 8.0f);
        t = t / 2.7725887298583984f;
        t = t * 8.0f;
        add = 8 + (int)t;
        if (add > 15) add = 15;
    }
    btab[idx] = rb[(bucket + add) * NH + hh];
}

__global__ __launch_bounds__(256) void bias_out_k(const float* __restrict__ btab,
                                                  float* __restrict__ out2) {
    size_t idx = (size_t)blockIdx.x * 256 + threadIdx.x;
    if (idx >= (size_t)NH * SEQ * SEQ) return;
    int kk = (int)(idx & (SEQ - 1));
    int qq = (int)((idx >> 11) & (SEQ - 1));
    int hh = (int)(idx >> 22);
    out2[idx] = btab[hh * NRELS + (kk - qq) + 2047];
}

__global__ __launch_bounds__(256) void rms_split_k(const float* __restrict__ x,
                                                   const float* __restrict__ w,
                                                   __nv_bfloat16* __restrict__ hi,
                                                   __nv_bfloat16* __restrict__ lo) {
    const size_t base = (size_t)blockIdx.x * DMODEL;
    const int t = threadIdx.x;
    float v0 = x[base + t], v1 = x[base + t + 256];
    float ss = v0 * v0 + v1 * v1;
    #pragma unroll
    for (int off = 16; off; off >>= 1) ss += __shfl_xor_sync(0xffffffffu, ss, off);
    __shared__ float red[8];
    __shared__ float bval;
    if ((t & 31) == 0) red[t >> 5] = ss;
    __syncthreads();
    if (t == 0) {
        float tot = 0.f;
        #pragma unroll
        for (int i = 0; i < 8; i++) tot += red[i];
        bval = rsqrtf(tot * (1.0f / DMODEL) + 1e-6f);
    }
    __syncthreads();
    const float inv = bval;
    float y0 = w[t] * (v0 * inv);
    float y1 = w[t + 256] * (v1 * inv);
    __nv_bfloat16 h, l;
    split_bf16(y0, h, l);
    hi[base + t] = h; lo[base + t] = l;
    split_bf16(y1, h, l);
    hi[base + t + 256] = h; lo[base + t + 256] = l;
}

__global__ __launch_bounds__(256) void rms_k(const float* __restrict__ x,
                                             const float* __restrict__ w,
                                             float* __restrict__ y) {
    const size_t base = (size_t)blockIdx.x * DMODEL;
    const int t = threadIdx.x;
    float v0 = x[base + t], v1 = x[base + t + 256];
    float ss = v0 * v0 + v1 * v1;
    #pragma unroll
    for (int off = 16; off; off >>= 1) ss += __shfl_xor_sync(0xffffffffu, ss, off);
    __shared__ float red[8];
    __shared__ float bval;
    if ((t & 31) == 0) red[t >> 5] = ss;
    __syncthreads();
    if (t == 0) {
        float tot = 0.f;
        #pragma unroll
        for (int i = 0; i < 8; i++) tot += red[i];
        bval = rsqrtf(tot * (1.0f / DMODEL) + 1e-6f);
    }
    __syncthreads();
    const float inv = bval;
    y[base + t]       = w[t]       * (v0 * inv);
    y[base + t + 256] = w[t + 256] * (v1 * inv);
}

__global__ __launch_bounds__(256) void cvt_wt_all_k(const float* __restrict__ W,
                                                    __nv_bfloat16* __restrict__ th,
                                                    __nv_bfloat16* __restrict__ tl,
                                                    int Kd, int Nd,
                                                    size_t srcStride, size_t dstStride) {
    __shared__ float tile[32][33];
    const int l = blockIdx.z;
    W  += (size_t)l * srcStride;
    th += (size_t)l * dstStride;
    tl += (size_t)l * dstStride;
    int kb = blockIdx.y * 32, nb = blockIdx.x * 32;
    int tx = threadIdx.x & 31, ty = threadIdx.x >> 5;
    for (int r = ty; r < 32; r += 8)
        tile[r][tx] = W[(size_t)(kb + r) * Nd + nb + tx];
    __syncthreads();
    for (int r = ty; r < 32; r += 8) {
        float v = tile[tx][r];
        __nv_bfloat16 h, l2;
        split_bf16(v, h, l2);
        size_t oidx = (size_t)(nb + r) * Kd + kb + tx;
        th[oidx] = h;
        tl[oidx] = l2;
    }
}

// ---------------- warp-MMA bf16x3 GEMM (3-stage cp.async, per-kk frags) ----------------
#define MG_ROWB   80
#define MG_TILE   (128 * MG_ROWB)
#define MG_BUF    (4 * MG_TILE)
#define MG_SMEM3  (3 * MG_BUF)     // 122880

template <int EPI>
__global__ __launch_bounds__(256) void mgemm_k(
    const __nv_bfloat16* __restrict__ ah, const __nv_bfloat16* __restrict__ al,
    const __nv_bfloat16* __restrict__ wh, const __nv_bfloat16* __restrict__ wl,
    float* C0, float* C1, float* C2,
    const float* __restrict__ E, int K, int ldc, size_t wSlot)
{
    extern __shared__ char smem[];
    const uint32_t sb = smem_u32(smem);
    const int t = threadIdx.x;
    const int lane = t & 31, wid = t >> 5;
    const int wr = wid & 1, wc = wid >> 1;
    const int z = blockIdx.z;
    const __nv_bfloat16* Bh = wh + (size_t)z * wSlot;
    const __nv_bfloat16* Bl = wl + (size_t)z * wSlot;
    float* C = (z == 0) ? C0 : (z == 1) ? C1 : C2;
    const int m0 = blockIdx.y * 128, n0 = blockIdx.x * 128;

    float d[4][4][4];
    #pragma unroll
    for (int mi = 0; mi < 4; mi++)
        #pragma unroll
        for (int nj = 0; nj < 4; nj++)
            #pragma unroll
            for (int r = 0; r < 4; r++) d[mi][nj][r] = 0.f;

    const int lr = t >> 2;
    const int lc = t & 3;
    const __nv_bfloat16* srcs[4] = { ah, al, Bh, Bl };

    auto issue = [&](int kc, int buf) {
        const uint32_t base = sb + buf * MG_BUF;
        #pragma unroll
        for (int tile = 0; tile < 4; tile++) {
            const __nv_bfloat16* s = srcs[tile];
            const int baseRow = (tile < 2) ? m0 : n0;
            #pragma unroll
            for (int h = 0; h < 2; h++) {
                const int row = lr + h * 64;
                const __nv_bfloat16* g = s + (size_t)(baseRow + row) * K + kc * 32 + lc * 8;
                CP_ASYNC16(base + tile * MG_TILE + row * MG_ROWB + lc * 16, g);
            }
        }
        CP_COMMIT();
    };

    const int nch = K >> 5;
    issue(0, 0);
    issue(1, 1);

    const int mat = lane >> 3, l8 = lane & 7;
    for (int kc = 0; kc < nch; kc++) {
        const int buf = kc % 3;
        if (kc + 2 < nch) { issue(kc + 2, (kc + 2) % 3); cp_wait<2>(); }
        else if (kc + 1 < nch) cp_wait<1>();
        else cp_wait<0>();
        __syncthreads();
        const uint32_t bbase = sb + buf * MG_BUF;
        #pragma unroll
        for (int kk = 0; kk < 2; kk++) {
            uint32_t Ah[4][4], Al[4][4], Bhf[2][4], Blf[2][4];
            #pragma unroll
            for (int mi = 0; mi < 4; mi++) {
                const int row = wr * 64 + mi * 16 + (mat & 1) * 8 + l8;
                const uint32_t ad = bbase + row * MG_ROWB + kk * 32 + (mat >> 1) * 16;
                ldmx4(Ah[mi], ad);
                ldmx4(Al[mi], ad + MG_TILE);
            }
            #pragma unroll
            for (int nj2 = 0; nj2 < 2; nj2++) {
                const int n = wc * 32 + nj2 * 16 + (mat >> 1) * 8 + l8;
                const uint32_t bd = bbase + 2 * MG_TILE + n * MG_ROWB + kk * 32 + (mat & 1) * 16;
                ldmx4(Bhf[nj2], bd);
                ldmx4(Blf[nj2], bd + MG_TILE);
            }
            #pragma unroll
            for (int mi = 0; mi < 4; mi++)
                #pragma unroll
                for (int nj = 0; nj < 4; nj++) {
                    const int g = nj >> 1, o = (nj & 1) * 2;
                    mma16816(d[mi][nj], Ah[mi], Bhf[g][o], Bhf[g][o + 1]);
                    mma16816(d[mi][nj], Ah[mi], Blf[g][o], Blf[g][o + 1]);
                    mma16816(d[mi][nj], Al[mi], Bhf[g][o], Bhf[g][o + 1]);
                }
        }
        __syncthreads();
    }

    #pragma unroll
    for (int mi = 0; mi < 4; mi++) {
        #pragma unroll
        for (int nj = 0; nj < 4; nj++) {
            const int row = m0 + wr * 64 + mi * 16 + (lane >> 2);
            const int col = n0 + wc * 32 + nj * 8 + (lane & 3) * 2;
            #pragma unroll
            for (int hh = 0; hh < 2; hh++) {
                const int m = row + hh * 8;
                float2 cv = make_float2(d[mi][nj][hh * 2], d[mi][nj][hh * 2 + 1]);
                if constexpr (EPI == 1) {
                    const float2 rv = *reinterpret_cast<const float2*>(
                        E + (size_t)m * ldc + col);
                    cv.x += rv.x; cv.y += rv.y;
                }
                *reinterpret_cast<float2*>(C + (size_t)m * ldc + col) = cv;
            }
        }
    }
}

// QKV GEMM: all three outputs split bf16 (q, k, v same [row,512] layout).
__global__ __launch_bounds__(256) void mgemm_qkv_k(
    const __nv_bfloat16* __restrict__ ah, const __nv_bfloat16* __restrict__ al,
    const __nv_bfloat16* __restrict__ wh, const __nv_bfloat16* __restrict__ wl,
    __nv_bfloat16* __restrict__ qh, __nv_bfloat16* __restrict__ ql,
    __nv_bfloat16* __restrict__ kh, __nv_bfloat16* __restrict__ kl,
    __nv_bfloat16* __restrict__ vh, __nv_bfloat16* __restrict__ vl,
    size_t wSlot)
{
    constexpr int K = DMODEL;
    extern __shared__ char smem[];
    const uint32_t sb = smem_u32(smem);
    const int t = threadIdx.x;
    const int lane = t & 31, wid = t >> 5;
    const int wr = wid & 1, wc = wid >> 1;
    const int z = blockIdx.z;
    const __nv_bfloat16* Bh = wh + (size_t)z * wSlot;
    const __nv_bfloat16* Bl = wl + (size_t)z * wSlot;
    const int m0 = blockIdx.y * 128, n0 = blockIdx.x * 128;

    float d[4][4][4];
    #pragma unroll
    for (int mi = 0; mi < 4; mi++)
        #pragma unroll
        for (int nj = 0; nj < 4; nj++)
            #pragma unroll
            for (int r = 0; r < 4; r++) d[mi][nj][r] = 0.f;

    const int lr = t >> 2;
    const int lc = t & 3;
    const __nv_bfloat16* srcs[4] = { ah, al, Bh, Bl };

    auto issue = [&](int kc, int buf) {
        const uint32_t base = sb + buf * MG_BUF;
        #pragma unroll
        for (int tile = 0; tile < 4; tile++) {
            const __nv_bfloat16* s = srcs[tile];
            const int baseRow = (tile < 2) ? m0 : n0;
            #pragma unroll
            for (int h = 0; h < 2; h++) {
                const int row = lr + h * 64;
                const __nv_bfloat16* g = s + (size_t)(baseRow + row) * K + kc * 32 + lc * 8;
                CP_ASYNC16(base + tile * MG_TILE + row * MG_ROWB + lc * 16, g);
            }
        }
        CP_COMMIT();
    };

    const int nch = K >> 5;
    issue(0, 0);
    issue(1, 1);

    const int mat = lane >> 3, l8 = lane & 7;
    for (int kc = 0; kc < nch; kc++) {
        const int buf = kc % 3;
        if (kc + 2 < nch) { issue(kc + 2, (kc + 2) % 3); cp_wait<2>(); }
        else if (kc + 1 < nch) cp_wait<1>();
        else cp_wait<0>();
        __syncthreads();
        const uint32_t bbase = sb + buf * MG_BUF;
        #pragma unroll
        for (int kk = 0; kk < 2; kk++) {
            uint32_t Ah[4][4], Al[4][4], Bhf[2][4], Blf[2][4];
            #pragma unroll
            for (int mi = 0; mi < 4; mi++) {
                const int row = wr * 64 + mi * 16 + (mat & 1) * 8 + l8;
                const uint32_t ad = bbase + row * MG_ROWB + kk * 32 + (mat >> 1) * 16;
                ldmx4(Ah[mi], ad);
                ldmx4(Al[mi], ad + MG_TILE);
            }
            #pragma unroll
            for (int nj2 = 0; nj2 < 2; nj2++) {
                const int n = wc * 32 + nj2 * 16 + (mat >> 1) * 8 + l8;
                const uint32_t bd = bbase + 2 * MG_TILE + n * MG_ROWB + kk * 32 + (mat & 1) * 16;
                ldmx4(Bhf[nj2], bd);
                ldmx4(Blf[nj2], bd + MG_TILE);
            }
            #pragma unroll
            for (int mi = 0; mi < 4; mi++)
                #pragma unroll
                for (int nj = 0; nj < 4; nj++) {
                    const int g = nj >> 1, o = (nj & 1) * 2;
                    mma16816(d[mi][nj], Ah[mi], Bhf[g][o], Bhf[g][o + 1]);
                    mma16816(d[mi][nj], Ah[mi], Blf[g][o], Blf[g][o + 1]);
                    mma16816(d[mi][nj], Al[mi], Bhf[g][o], Bhf[g][o + 1]);
                }
        }
        __syncthreads();
    }

    __nv_bfloat16* H = (z == 0) ? qh : (z == 1) ? kh : vh;
    __nv_bfloat16* L = (z == 0) ? ql : (z == 1) ? kl : vl;
    #pragma unroll
    for (int mi = 0; mi < 4; mi++) {
        #pragma unroll
        for (int nj = 0; nj < 4; nj++) {
            const int row = m0 + wr * 64 + mi * 16 + (lane >> 2);
            const int col = n0 + wc * 32 + nj * 8 + (lane & 3) * 2;
            #pragma unroll
            for (int hh = 0; hh < 2; hh++) {
                const int m = row + hh * 8;
                const size_t off = (size_t)m * DMODEL + col;
                split_store2(d[mi][nj][hh * 2], d[mi][nj][hh * 2 + 1],
                             H + off, L + off);
            }
        }
    }
}

// FFN-in fused: gelu(A@W0) * (A@W1), split bf16 out. 3-stage.
#define FFN_BUF  (6 * MG_TILE)
#define FFN_SMEM3 (3 * FFN_BUF)    // 184320
__global__ __launch_bounds__(256) void mgemm_ffn_k(
    const __nv_bfloat16* __restrict__ ah, const __nv_bfloat16* __restrict__ al,
    const __nv_bfloat16* __restrict__ w0h, const __nv_bfloat16* __restrict__ w0l,
    const __nv_bfloat16* __restrict__ w1h, const __nv_bfloat16* __restrict__ w1l,
    __nv_bfloat16* __restrict__ Ghi, __nv_bfloat16* __restrict__ Glo)
{
    constexpr int K = DMODEL;
    extern __shared__ char smem[];
    const uint32_t sb = smem_u32(smem);
    const int t = threadIdx.x;
    const int lane = t & 31, wid = t >> 5;
    const int wr = wid & 1, wc = wid >> 1;
    const int m0 = blockIdx.y * 128, n0 = blockIdx.x * 128;

    float d0[4][4][4], d1[4][4][4];
    #pragma unroll
    for (int mi = 0; mi < 4; mi++)
        #pragma unroll
        for (int nj = 0; nj < 4; nj++)
            #pragma unroll
            for (int r = 0; r < 4; r++) { d0[mi][nj][r] = 0.f; d1[mi][nj][r] = 0.f; }

    const int lr = t >> 2;
    const int lc = t & 3;
    const __nv_bfloat16* srcs[6] = { ah, al, w0h, w0l, w1h, w1l };

    auto issue = [&](int kc, int buf) {
        const uint32_t base = sb + buf * FFN_BUF;
        #pragma unroll
        for (int tile = 0; tile < 6; tile++) {
            const __nv_bfloat16* s = srcs[tile];
            const int baseRow = (tile < 2) ? m0 : n0;
            #pragma unroll
            for (int h = 0; h < 2; h++) {
                const int row = lr + h * 64;
                const __nv_bfloat16* g = s + (size_t)(baseRow + row) * K + kc * 32 + lc * 8;
                CP_ASYNC16(base + tile * MG_TILE + row * MG_ROWB + lc * 16, g);
            }
        }
        CP_COMMIT();
    };

    const int nch = K >> 5;
    issue(0, 0);
    issue(1, 1);

    const int mat = lane >> 3, l8 = lane & 7;
    for (int kc = 0; kc < nch; kc++) {
        const int buf = kc % 3;
        if (kc + 2 < nch) { issue(kc + 2, (kc + 2) % 3); cp_wait<2>(); }
        else if (kc + 1 < nch) cp_wait<1>();
        else cp_wait<0>();
        __syncthreads();
        const uint32_t bbase = sb + buf * FFN_BUF;
        #pragma unroll
        for (int kk = 0; kk < 2; kk++) {
            uint32_t Ah[4][4], Al[4][4];
            #pragma unroll
            for (int mi = 0; mi < 4; mi++) {
                const int row = wr * 64 + mi * 16 + (mat & 1) * 8 + l8;
                const uint32_t ad = bbase + row * MG_ROWB + kk * 32 + (mat >> 1) * 16;
                ldmx4(Ah[mi], ad);
                ldmx4(Al[mi], ad + MG_TILE);
            }
            #pragma unroll
            for (int w = 0; w < 2; w++) {
                uint32_t Bhf[2][4], Blf[2][4];
                const uint32_t boff = bbase + (2 + 2 * w) * MG_TILE;
                #pragma unroll
                for (int nj2 = 0; nj2 < 2; nj2++) {
                    const int n = wc * 32 + nj2 * 16 + (mat >> 1) * 8 + l8;
                    const uint32_t bd = boff + n * MG_ROWB + kk * 32 + (mat & 1) * 16;
                    ldmx4(Bhf[nj2], bd);
                    ldmx4(Blf[nj2], bd + MG_TILE);
                }
                #pragma unroll
                for (int mi = 0; mi < 4; mi++)
                    #pragma unroll
                    for (int nj = 0; nj < 4; nj++) {
                        float* dd = w ? d1[mi][nj] : d0[mi][nj];
                        const int g = nj >> 1, o = (nj & 1) * 2;
                        mma16816(dd, Ah[mi], Bhf[g][o], Bhf[g][o + 1]);
                        mma16816(dd, Ah[mi], Blf[g][o], Blf[g][o + 1]);
                        mma16816(dd, Al[mi], Bhf[g][o], Bhf[g][o + 1]);
                    }
            }
        }
        __syncthreads();
    }

    #pragma unroll
    for (int mi = 0; mi < 4; mi++) {
        #pragma unroll
        for (int nj = 0; nj < 4; nj++) {
            const int row = m0 + wr * 64 + mi * 16 + (lane >> 2);
            const int col = n0 + wc * 32 + nj * 8 + (lane & 3) * 2;
            #pragma unroll
            for (int hh = 0; hh < 2; hh++) {
                const int m = row + hh * 8;
                const size_t off = (size_t)m * DFF_ + col;
                float r0 = gelu_new(d0[mi][nj][hh * 2])     * d1[mi][nj][hh * 2];
                float r1 = gelu_new(d0[mi][nj][hh * 2 + 1]) * d1[mi][nj][hh * 2 + 1];
                split_store2(r0, r1, Ghi + off, Glo + off);
            }
        }
    }
}

// ---------------- fused flash attention (unchanged from R14) ----------------
#define FL_QSTR 144
#define FL_QT   (128 * FL_QSTR)
#define FL_OFF_K(buf) (2 * FL_QT + (buf) * 2 * FL_QT)
#define FL_OFF_V(buf) (6 * FL_QT + (buf) * 2 * FL_QT)
#define FL_BIAS_OFF (10 * FL_QT)          // 184320
#define FL_SMEM (FL_BIAS_OFF + 16384)     // 200704
__global__ __launch_bounds__(256) void flash_k(
    const __nv_bfloat16* __restrict__ qh_g, const __nv_bfloat16* __restrict__ ql_g,
    const __nv_bfloat16* __restrict__ kh_g, const __nv_bfloat16* __restrict__ kl_g,
    const __nv_bfloat16* __restrict__ vh_g, const __nv_bfloat16* __restrict__ vl_g,
    const float* __restrict__ btab,
    __nv_bfloat16* __restrict__ Ohi, __nv_bfloat16* __restrict__ Olo)
{
    extern __shared__ char smem[];
    const uint32_t sb = smem_u32(smem);
    float* smb = reinterpret_cast<float*>(smem + FL_BIAS_OFF);
    const int t = threadIdx.x, lane = t & 31, wid = t >> 5;
    const int z = blockIdx.z, zb = z >> 3, zh = z & 7;
    const int m0 = blockIdx.x * 128;
    const int mat = lane >> 3, l8 = lane & 7;

    auto loadQ = [&]() {
        #pragma unroll
        for (int i = 0; i < 4; i++) {
            int idx = t + i * 256, row = idx >> 3, c = idx & 7;
            size_t go = (size_t)(zb * SEQ + m0 + row) * DMODEL + zh * 64 + c * 8;
            CP_ASYNC16(sb + row * FL_QSTR + c * 16, qh_g + go);
            CP_ASYNC16(sb + FL_QT + row * FL_QSTR + c * 16, ql_g + go);
        }
    };
    auto loadKV = [&](int kt, int buf) {
        #pragma unroll
        for (int i = 0; i < 4; i++) {
            int idx = t + i * 256, row = idx >> 3, c = idx & 7;
            size_t go = (size_t)(zb * SEQ + kt * 128 + row) * DMODEL + zh * 64 + c * 8;
            CP_ASYNC16(sb + FL_OFF_K(buf) + row * FL_QSTR + c * 16, kh_g + go);
            CP_ASYNC16(sb + FL_OFF_K(buf) + FL_QT + row * FL_QSTR + c * 16, kl_g + go);
            CP_ASYNC16(sb + FL_OFF_V(buf) + row * FL_QSTR + c * 16, vh_g + go);
            CP_ASYNC16(sb + FL_OFF_V(buf) + FL_QT + row * FL_QSTR + c * 16, vl_g + go);
        }
        CP_COMMIT();
    };

    loadQ();
    loadKV(0, 0);
    for (int i = t; i < NRELS; i += 256) smb[i] = btab[zh * NRELS + i];

    float m_[2] = { -1e30f, -1e30f }, l_[2] = { 0.f, 0.f };
    float o[8][4];
    #pragma unroll
    for (int nt = 0; nt < 8; nt++)
        #pragma unroll
        for (int e = 0; e < 4; e++) o[nt][e] = 0.f;
    uint32_t qh[4][4], ql[4][4];

    for (int kt = 0; kt < 16; kt++) {
        const int buf = kt & 1;
        if (kt + 1 < 16) { loadKV(kt + 1, buf ^ 1); cp_wait<1>(); }
        else             { cp_wait<0>(); }
        __syncthreads();
        if (kt == 0) {
            #pragma unroll
            for (int kc = 0; kc < 4; kc++) {
                const int row = wid * 16 + (mat & 1) * 8 + l8;
                const uint32_t ad = sb + row * FL_QSTR + kc * 32 + (mat >> 1) * 16;
                ldmx4(qh[kc], ad);
                ldmx4(ql[kc], ad + FL_QT);
            }
        }
        float s[16][4];
        #pragma unroll
        for (int j = 0; j < 16; j++)
            #pragma unroll
            for (int e = 0; e < 4; e++) s[j][e] = 0.f;
        #pragma unroll
        for (int j2 = 0; j2 < 8; j2++) {
            const int n = j2 * 16 + (mat >> 1) * 8 + l8;
            #pragma unroll
            for (int kc = 0; kc < 4; kc++) {
                uint32_t bh4[4], bl4[4];
                const uint32_t bd = sb + FL_OFF_K(buf) + n * FL_QSTR + kc * 32 + (mat & 1) * 16;
                ldmx4(bh4, bd);
                ldmx4(bl4, bd + FL_QT);
                #pragma unroll
                for (int e = 0; e < 2; e++) {
                    mma16816(s[j2 * 2 + e], qh[kc], bh4[e * 2], bh4[e * 2 + 1]);
                    mma16816(s[j2 * 2 + e], qh[kc], bl4[e * 2], bl4[e * 2 + 1]);
                    mma16816(s[j2 * 2 + e], ql[kc], bh4[e * 2], bh4[e * 2 + 1]);
                }
            }
        }
        const int r0 = m0 + wid * 16 + (lane >> 2);
        const int relbase = kt * 128 + 2 * (lane & 3) - r0 + 2047;
        #pragma unroll
        for (int j = 0; j < 16; j++) {
            const int idx = relbase + j * 8;
            s[j][0] += smb[idx];     s[j][1] += smb[idx + 1];
            s[j][2] += smb[idx - 8]; s[j][3] += smb[idx - 7];
        }
        float mx[2] = { -1e30f, -1e30f };
        #pragma unroll
        for (int j = 0; j < 16; j++) {
            mx[0] = fmaxf(mx[0], fmaxf(s[j][0], s[j][1]));
            mx[1] = fmaxf(mx[1], fmaxf(s[j][2], s[j][3]));
        }
        #pragma unroll
        for (int off = 1; off <= 2; off <<= 1) {
            mx[0] = fmaxf(mx[0], __shfl_xor_sync(0xffffffffu, mx[0], off));
            mx[1] = fmaxf(mx[1], __shfl_xor_sync(0xffffffffu, mx[1], off));
        }
        float al2[2];
        #pragma unroll
        for (int h = 0; h < 2; h++) {
            const float nm = fmaxf(m_[h], mx[h]);
            al2[h] = __expf(m_[h] - nm);
            m_[h] = nm;
        }
        float rs[2] = { 0.f, 0.f };
        #pragma unroll
        for (int j = 0; j < 16; j++) {
            s[j][0] = __expf(s[j][0] - m_[0]);
            s[j][1] = __expf(s[j][1] - m_[0]);
            s[j][2] = __expf(s[j][2] - m_[1]);
            s[j][3] = __expf(s[j][3] - m_[1]);
            rs[0] += s[j][0] + s[j][1];
            rs[1] += s[j][2] + s[j][3];
        }
        #pragma unroll
        for (int off = 1; off <= 2; off <<= 1) {
            rs[0] += __shfl_xor_sync(0xffffffffu, rs[0], off);
            rs[1] += __shfl_xor_sync(0xffffffffu, rs[1], off);
        }
        l_[0] = l_[0] * al2[0] + rs[0];
        l_[1] = l_[1] * al2[1] + rs[1];
        #pragma unroll
        for (int nt = 0; nt < 8; nt++) {
            o[nt][0] *= al2[0]; o[nt][1] *= al2[0];
            o[nt][2] *= al2[1]; o[nt][3] *= al2[1];
        }
        #pragma unroll
        for (int kc2 = 0; kc2 < 8; kc2++) {
            uint32_t pa[4], pl[4];
            #pragma unroll
            for (int u = 0; u < 2; u++) {
                #pragma unroll
                for (int hh = 0; hh < 2; hh++) {
                    const float v0 = s[2 * kc2 + u][hh * 2];
                    const float v1 = s[2 * kc2 + u][hh * 2 + 1];
                    __nv_bfloat16 h0, h1, lo0, lo1;
                    split_bf16(v0, h0, lo0);
                    split_bf16(v1, h1, lo1);
                    pa[u * 2 + hh] = pack_bf(h0, h1);
                    pl[u * 2 + hh] = pack_bf(lo0, lo1);
                }
            }
            #pragma unroll
            for (int j2v = 0; j2v < 4; j2v++) {
                uint32_t vh4[4], vl4[4];
                const uint32_t bd = sb + FL_OFF_V(buf)
                    + (kc2 * 16 + (mat & 1) * 8 + l8) * FL_QSTR
                    + (j2v * 16 + (mat >> 1) * 8) * 2;
                ldmx4t(vh4, bd);
                ldmx4t(vl4, bd + FL_QT);
                #pragma unroll
                for (int e = 0; e < 2; e++) {
                    const int nt = j2v * 2 + e;
                    mma16816(o[nt], pa, vh4[e * 2], vh4[e * 2 + 1]);
                    mma16816(o[nt], pa, vl4[e * 2], vl4[e * 2 + 1]);
                    mma16816(o[nt], pl, vh4[e * 2], vh4[e * 2 + 1]);
                }
            }
        }
        __syncthreads();
    }

    const float inv0 = 1.0f / l_[0], inv1 = 1.0f / l_[1];
    const int r0 = m0 + wid * 16 + (lane >> 2);
    #pragma unroll
    for (int nt = 0; nt < 8; nt++) {
        const int col = zh * 64 + nt * 8 + 2 * (lane & 3);
        const size_t o0 = (size_t)(zb * SEQ + r0) * DMODEL + col;
        const size_t o1 = (size_t)(zb * SEQ + r0 + 8) * DMODEL + col;
        split_store2(o[nt][0] * inv0, o[nt][1] * inv0, Ohi + o0, Olo + o0);
        split_store2(o[nt][2] * inv1, o[nt][3] * inv1, Ohi + o1, Olo + o1);
    }
}

// ---------------- launch ----------------
extern "C" void kernel_launch(void* const* d_in, const int* in_sizes, int n_in,
                              void* d_out, int out_size) {
    const int*   ids    = (const int*)  d_in[0];
    const float* embed  = (const float*)d_in[1];
    const float* Wq     = (const float*)d_in[2];
    const float* Wk     = (const float*)d_in[3];
    const float* Wv     = (const float*)d_in[4];
    const float* Wo     = (const float*)d_in[5];
    const float* relb   = (const float*)d_in[6];
    const float* wi0    = (const float*)d_in[7];
    const float* wi1    = (const float*)d_in[8];
    const float* wo_ffn = (const float*)d_in[9];
    const float* ln0    = (const float*)d_in[10];
    const float* ln1    = (const float*)d_in[11];
    const float* flw    = (const float*)d_in[12];
    float* out = (float*)d_out;

    float *x, *f0, *f1, *btab;
    __nv_bfloat16 *ah, *al, *oh, *ol, *vh, *vl, *wh, *wl;
    cudaGetSymbolAddress((void**)&x,  g_x);
    cudaGetSymbolAddress((void**)&f0, g_f0);
    cudaGetSymbolAddress((void**)&f1, g_f1);
    cudaGetSymbolAddress((void**)&btab, g_btab);
    cudaGetSymbolAddress((void**)&ah, g_ah);
    cudaGetSymbolAddress((void**)&al, g_al);
    cudaGetSymbolAddress((void**)&oh, g_oh);
    cudaGetSymbolAddress((void**)&ol, g_ol);
    cudaGetSymbolAddress((void**)&vh, g_vh);
    cudaGetSymbolAddress((void**)&vl, g_vl);
    cudaGetSymbolAddress((void**)&wh, g_wh);
    cudaGetSymbolAddress((void**)&wl, g_wl);
    __nv_bfloat16* gh = (__nv_bfloat16*)f0;
    __nv_bfloat16* gl = (__nv_bfloat16*)f1;

    cudaFuncSetAttribute(mgemm_k<0>, cudaFuncAttributeMaxDynamicSharedMemorySize, MG_SMEM3);
    cudaFuncSetAttribute(mgemm_k<1>, cudaFuncAttributeMaxDynamicSharedMemorySize, MG_SMEM3);
    cudaFuncSetAttribute(mgemm_qkv_k, cudaFuncAttributeMaxDynamicSharedMemorySize, MG_SMEM3);
    cudaFuncSetAttribute(mgemm_ffn_k, cudaFuncAttributeMaxDynamicSharedMemorySize, FFN_SMEM3);
    cudaFuncSetAttribute(flash_k, cudaFuncAttributeMaxDynamicSharedMemorySize, FL_SMEM);

    float* out_bias = ((size_t)out_size > OUTX) ? (out + OUTX) : nullptr;

    embed_k<<<NROWS, 256>>>(ids, embed, x);
    bias_tab_k<<<(NH * NRELS + 255) / 256, 256>>>(relb, btab);
    if (out_bias) {
        size_t nb = ((size_t)NH * SEQ * SEQ + 255) / 256;
        bias_out_k<<<(unsigned)nb, 256>>>(btab, out_bias);
    }
    {
        dim3 gQ(DMODEL / 32, DMODEL / 32, NL);
        cvt_wt_all_k<<<gQ, 256>>>(Wq, wh,            wl,            DMODEL, DMODEL, DDc, DDc);
        cvt_wt_all_k<<<gQ, 256>>>(Wk, wh + 4 * DDc,  wl + 4 * DDc,  DMODEL, DMODEL, DDc, DDc);
        cvt_wt_all_k<<<gQ, 256>>>(Wv, wh + 8 * DDc,  wl + 8 * DDc,  DMODEL, DMODEL, DDc, DDc);
        cvt_wt_all_k<<<gQ, 256>>>(Wo, wh + 12 * DDc, wl + 12 * DDc, DMODEL, DMODEL, DDc, DDc);
        dim3 gF(DFF_ / 32, DMODEL / 32, NL);
        cvt_wt_all_k<<<gF, 256>>>(wi0, wh + 16 * DDc,           wl + 16 * DDc,           DMODEL, DFF_, DFc, DFc);
        cvt_wt_all_k<<<gF, 256>>>(wi1, wh + 16 * DDc + 4 * DFc, wl + 16 * DDc + 4 * DFc, DMODEL, DFF_, DFc, DFc);
        dim3 gO(DMODEL / 32, DFF_ / 32, NL);
        cvt_wt_all_k<<<gO, 256>>>(wo_ffn, wh + 16 * DDc + 8 * DFc, wl + 16 * DDc + 8 * DFc, DFF_, DMODEL, DFc, DFc);
    }

    for (int i = 0; i < NL; i++) {
        const size_t wQKV = (size_t)i * DDc;
        const size_t wO   = 12 * DDc + (size_t)i * DDc;
        const size_t wI0  = 16 * DDc + (size_t)i * DFc;
        const size_t wI1  = 16 * DDc + 4 * DFc + (size_t)i * DFc;
        const size_t wOF  = 16 * DDc + 8 * DFc + (size_t)i * DFc;
        // ---- self attention ----
        rms_split_k<<<NROWS, 256>>>(x, ln0 + (size_t)i * DMODEL, ah, al);
        mgemm_qkv_k<<<dim3(4, 32, 3), 256, MG_SMEM3>>>(ah, al, wh + wQKV, wl + wQKV,
                                                       oh, ol,
                                                       ah + QKSZ, al + QKSZ,
                                                       vh, vl, 4 * DDc);
        flash_k<<<dim3(SEQ / 128, 1, BATCH * NH), 256, FL_SMEM>>>(
            oh, ol, ah + QKSZ, al + QKSZ, vh, vl, btab, ah, al);
        mgemm_k<1><<<dim3(4, 32, 1), 256, MG_SMEM3>>>(ah, al, wh + wO, wl + wO,
                                                      x, x, x, x,
                                                      DMODEL, DMODEL, 0);
        // ---- gated-GELU FFN (fused) ----
        rms_split_k<<<NROWS, 256>>>(x, ln1 + (size_t)i * DMODEL, ah, al);
        mgemm_ffn_k<<<dim3(DFF_ / 128, NROWS / 128), 256, FFN_SMEM3>>>(
            ah, al, wh + wI0, wl + wI0, wh + wI1, wl + wI1, gh, gl);
        mgemm_k<1><<<dim3(4, 32, 1), 256, MG_SMEM3>>>(gh, gl, wh + wOF, wl + wOF,
                                                      x, x, x, x,
                                                      DFF_, DMODEL, 0);
    }
    rms_k<<<NROWS, 256>>>(x, flw, out);
}

// round 16
// speedup vs baseline: 1.0234x; 1.0234x over previous
#include <cuda_runtime.h>
#include <cuda_bf16.h>
#include <cstdint>
#include <math.h>

#define NL    4
#define DMODEL 512
#define NH    8
#define DHEAD 64
#define DFF_  1024
#define SEQ   2048
#define BATCH 2
#define NROWS (BATCH*SEQ)          // 4096
#define OUTX  ((size_t)NROWS*DMODEL)  // 2097152
#define QKSZ  ((size_t)NROWS*DMODEL)  // 2M elements
#define NRELS 4095

#define DDc   ((size_t)DMODEL*DMODEL)  // 262144
#define DFc   ((size_t)DMODEL*DFF_)    // 524288
#define WARENA (16*DDc + 12*DFc)

typedef unsigned long long u64;

// ---------------- scratch ----------------
__device__ float g_x [NROWS*DMODEL];
__device__ float g_f0[NROWS*DFF_];      // reused as bf16 hi for geglu output
__device__ float g_f1[NROWS*DFF_];      // reused as bf16 lo
__device__ float g_btab[NH*NRELS];      // per-head rel-bias table
__device__ __nv_bfloat16 g_ah[NROWS*DFF_];
__device__ __nv_bfloat16 g_al[NROWS*DFF_];
__device__ __nv_bfloat16 g_oh[NROWS*DMODEL];
__device__ __nv_bfloat16 g_ol[NROWS*DMODEL];
__device__ __nv_bfloat16 g_vh[NROWS*DMODEL];    // V split, [row, 512] layout
__device__ __nv_bfloat16 g_vl[NROWS*DMODEL];
__device__ __nv_bfloat16 g_wh[WARENA];
__device__ __nv_bfloat16 g_wl[WARENA];

// ---------------- helpers ----------------
__device__ __forceinline__ uint32_t smem_u32(const void* p) {
    uint32_t a;
    asm("{ .reg .u64 t; cvta.to.shared.u64 t, %1; cvt.u32.u64 %0, t; }" : "=r"(a) : "l"(p));
    return a;
}
#define CP_ASYNC16(sa, ga) \
    asm volatile("cp.async.cg.shared.global [%0], [%1], 16;" :: "r"(sa), "l"(ga))
#define CP_COMMIT() asm volatile("cp.async.commit_group;" ::: "memory")
template <int N>
__device__ __forceinline__ void cp_wait() {
    asm volatile("cp.async.wait_group %0;" :: "n"(N) : "memory");
}
__device__ __forceinline__ void ldmx4(uint32_t* r, uint32_t addr) {
    asm volatile("ldmatrix.sync.aligned.m8n8.x4.shared.b16 {%0,%1,%2,%3}, [%4];"
                 : "=r"(r[0]), "=r"(r[1]), "=r"(r[2]), "=r"(r[3]) : "r"(addr));
}
__device__ __forceinline__ void ldmx4t(uint32_t* r, uint32_t addr) {
    asm volatile("ldmatrix.sync.aligned.m8n8.x4.trans.shared.b16 {%0,%1,%2,%3}, [%4];"
                 : "=r"(r[0]), "=r"(r[1]), "=r"(r[2]), "=r"(r[3]) : "r"(addr));
}
__device__ __forceinline__ void mma16816(float* d, const uint32_t* a,
                                         uint32_t b0, uint32_t b1) {
    asm volatile(
        "mma.sync.aligned.m16n8k16.row.col.f32.bf16.bf16.f32 "
        "{%0,%1,%2,%3}, {%4,%5,%6,%7}, {%8,%9}, {%0,%1,%2,%3};"
        : "+f"(d[0]), "+f"(d[1]), "+f"(d[2]), "+f"(d[3])
        : "r"(a[0]), "r"(a[1]), "r"(a[2]), "r"(a[3]), "r"(b0), "r"(b1));
}
__device__ __forceinline__ uint32_t pack_bf(__nv_bfloat16 a, __nv_bfloat16 b) {
    __nv_bfloat162 p(a, b);
    return *reinterpret_cast<uint32_t*>(&p);
}
__device__ __forceinline__ void split_bf16(float v, __nv_bfloat16& h, __nv_bfloat16& l) {
    h = __float2bfloat16(v);
    l = __float2bfloat16(v - __bfloat162float(h));
}
__device__ __forceinline__ void split_store2(float a, float b,
                                             __nv_bfloat16* hi, __nv_bfloat16* lo) {
    __nv_bfloat16 h0, h1, l0, l1;
    split_bf16(a, h0, l0);
    split_bf16(b, h1, l1);
    *reinterpret_cast<uint32_t*>(hi) = pack_bf(h0, h1);
    *reinterpret_cast<uint32_t*>(lo) = pack_bf(l0, l1);
}
__device__ __forceinline__ float gelu_new(float xx) {
    float inner = 0.7978845608028654f * (xx + 0.044715f * (xx * xx * xx));
    return 0.5f * xx * (1.0f + tanhf(inner));
}

// ---------------- small kernels ----------------
__global__ __launch_bounds__(256) void embed_k(const int* __restrict__ ids,
                                               const float* __restrict__ emb,
                                               float* __restrict__ x) {
    const int row = blockIdx.x;
    const size_t src = (size_t)ids[row] * DMODEL;
    const size_t dst = (size_t)row * DMODEL;
    for (int i = threadIdx.x; i < DMODEL; i += 256) x[dst + i] = emb[src + i];
}

__global__ __launch_bounds__(256) void bias_tab_k(const float* __restrict__ rb,
                                                  float* __restrict__ btab) {
    int idx = blockIdx.x * 256 + threadIdx.x;
    if (idx >= NH * NRELS) return;
    int hh = idx / NRELS;
    int rel = (idx % NRELS) - 2047;
    int bucket = (rel > 0) ? 16 : 0;
    int rp = (rel < 0) ? -rel : rel;
    int add;
    if (rp < 8) {
        add = rp;
    } else {
        float t = logf((float)rp / 8.0f);
        t = t / 2.7725887298583984f;
        t = t * 8.0f;
        add = 8 + (int)t;
        if (add > 15) add = 15;
    }
    btab[idx] = rb[(bucket + add) * NH + hh];
}

__global__ __launch_bounds__(256) void bias_out_k(const float* __restrict__ btab,
                                                  float* __restrict__ out2) {
    size_t idx = (size_t)blockIdx.x * 256 + threadIdx.x;
    if (idx >= (size_t)NH * SEQ * SEQ) return;
    int kk = (int)(idx & (SEQ - 1));
    int qq = (int)((idx >> 11) & (SEQ - 1));
    int hh = (int)(idx >> 22);
    out2[idx] = btab[hh * NRELS + (kk - qq) + 2047];
}

__global__ __launch_bounds__(256) void rms_split_k(const float* __restrict__ x,
                                                   const float* __restrict__ w,
                                                   __nv_bfloat16* __restrict__ hi,
                                                   __nv_bfloat16* __restrict__ lo) {
    const size_t base = (size_t)blockIdx.x * DMODEL;
    const int t = threadIdx.x;
    float v0 = x[base + t], v1 = x[base + t + 256];
    float ss = v0 * v0 + v1 * v1;
    #pragma unroll
    for (int off = 16; off; off >>= 1) ss += __shfl_xor_sync(0xffffffffu, ss, off);
    __shared__ float red[8];
    __shared__ float bval;
    if ((t & 31) == 0) red[t >> 5] = ss;
    __syncthreads();
    if (t == 0) {
        float tot = 0.f;
        #pragma unroll
        for (int i = 0; i < 8; i++) tot += red[i];
        bval = rsqrtf(tot * (1.0f / DMODEL) + 1e-6f);
    }
    __syncthreads();
    const float inv = bval;
    float y0 = w[t] * (v0 * inv);
    float y1 = w[t + 256] * (v1 * inv);
    __nv_bfloat16 h, l;
    split_bf16(y0, h, l);
    hi[base + t] = h; lo[base + t] = l;
    split_bf16(y1, h, l);
    hi[base + t + 256] = h; lo[base + t + 256] = l;
}

__global__ __launch_bounds__(256) void rms_k(const float* __restrict__ x,
                                             const float* __restrict__ w,
                                             float* __restrict__ y) {
    const size_t base = (size_t)blockIdx.x * DMODEL;
    const int t = threadIdx.x;
    float v0 = x[base + t], v1 = x[base + t + 256];
    float ss = v0 * v0 + v1 * v1;
    #pragma unroll
    for (int off = 16; off; off >>= 1) ss += __shfl_xor_sync(0xffffffffu, ss, off);
    __shared__ float red[8];
    __shared__ float bval;
    if ((t & 31) == 0) red[t >> 5] = ss;
    __syncthreads();
    if (t == 0) {
        float tot = 0.f;
        #pragma unroll
        for (int i = 0; i < 8; i++) tot += red[i];
        bval = rsqrtf(tot * (1.0f / DMODEL) + 1e-6f);
    }
    __syncthreads();
    const float inv = bval;
    y[base + t]       = w[t]       * (v0 * inv);
    y[base + t + 256] = w[t + 256] * (v1 * inv);
}

// merged weight transpose+split: z = mat*NL + layer (up to 4 matrices, same shape)
__global__ __launch_bounds__(256) void cvt_wt_multi_k(
    const float* __restrict__ W0, const float* __restrict__ W1,
    const float* __restrict__ W2, const float* __restrict__ W3,
    __nv_bfloat16* __restrict__ th, __nv_bfloat16* __restrict__ tl,
    int Kd, int Nd) {
    __shared__ float tile[32][33];
    const int mat = blockIdx.z >> 2;
    const int l = blockIdx.z & 3;
    const size_t sz = (size_t)Kd * Nd;
    const float* W = ((mat == 0) ? W0 : (mat == 1) ? W1 : (mat == 2) ? W2 : W3)
                     + (size_t)l * sz;
    const size_t doff = (size_t)(mat * NL + l) * sz;
    th += doff;
    tl += doff;
    int kb = blockIdx.y * 32, nb = blockIdx.x * 32;
    int tx = threadIdx.x & 31, ty = threadIdx.x >> 5;
    for (int r = ty; r < 32; r += 8)
        tile[r][tx] = W[(size_t)(kb + r) * Nd + nb + tx];
    __syncthreads();
    for (int r = ty; r < 32; r += 8) {
        float v = tile[tx][r];
        __nv_bfloat16 h, l2;
        split_bf16(v, h, l2);
        size_t oidx = (size_t)(nb + r) * Kd + kb + tx;
        th[oidx] = h;
        tl[oidx] = l2;
    }
}

// ---------------- warp-MMA bf16x3 GEMM (R14: 2-stage, per-kk frags) ----------------
#define MG_ROWB   80
#define MG_TILE   (128 * MG_ROWB)
#define MG_BUF    (4 * MG_TILE)
#define MG_SMEM   (2 * MG_BUF)

template <int EPI>
__global__ __launch_bounds__(256) void mgemm_k(
    const __nv_bfloat16* __restrict__ ah, const __nv_bfloat16* __restrict__ al,
    const __nv_bfloat16* __restrict__ wh, const __nv_bfloat16* __restrict__ wl,
    float* C0, float* C1, float* C2,
    const float* __restrict__ E, int K, int ldc, size_t wSlot)
{
    extern __shared__ char smem[];
    const uint32_t sb = smem_u32(smem);
    const int t = threadIdx.x;
    const int lane = t & 31, wid = t >> 5;
    const int wr = wid & 1, wc = wid >> 1;
    const int z = blockIdx.z;
    const __nv_bfloat16* Bh = wh + (size_t)z * wSlot;
    const __nv_bfloat16* Bl = wl + (size_t)z * wSlot;
    float* C = (z == 0) ? C0 : (z == 1) ? C1 : C2;
    const int m0 = blockIdx.y * 128, n0 = blockIdx.x * 128;

    float d[4][4][4];
    #pragma unroll
    for (int mi = 0; mi < 4; mi++)
        #pragma unroll
        for (int nj = 0; nj < 4; nj++)
            #pragma unroll
            for (int r = 0; r < 4; r++) d[mi][nj][r] = 0.f;

    const int lr = t >> 2;
    const int lc = t & 3;
    const __nv_bfloat16* srcs[4] = { ah, al, Bh, Bl };

    auto issue = [&](int kc, int buf) {
        const uint32_t base = sb + buf * MG_BUF;
        #pragma unroll
        for (int tile = 0; tile < 4; tile++) {
            const __nv_bfloat16* s = srcs[tile];
            const int baseRow = (tile < 2) ? m0 : n0;
            #pragma unroll
            for (int h = 0; h < 2; h++) {
                const int row = lr + h * 64;
                const __nv_bfloat16* g = s + (size_t)(baseRow + row) * K + kc * 32 + lc * 8;
                CP_ASYNC16(base + tile * MG_TILE + row * MG_ROWB + lc * 16, g);
            }
        }
        CP_COMMIT();
    };

    const int nch = K >> 5;
    issue(0, 0);

    const int mat = lane >> 3, l8 = lane & 7;
    for (int kc = 0; kc < nch; kc++) {
        const int buf = kc & 1;
        if (kc + 1 < nch) { issue(kc + 1, buf ^ 1); cp_wait<1>(); }
        else              { cp_wait<0>(); }
        __syncthreads();
        const uint32_t bbase = sb + buf * MG_BUF;
        #pragma unroll
        for (int kk = 0; kk < 2; kk++) {
            uint32_t Ah[4][4], Al[4][4], Bhf[2][4], Blf[2][4];
            #pragma unroll
            for (int mi = 0; mi < 4; mi++) {
                const int row = wr * 64 + mi * 16 + (mat & 1) * 8 + l8;
                const uint32_t ad = bbase + row * MG_ROWB + kk * 32 + (mat >> 1) * 16;
                ldmx4(Ah[mi], ad);
                ldmx4(Al[mi], ad + MG_TILE);
            }
            #pragma unroll
            for (int nj2 = 0; nj2 < 2; nj2++) {
                const int n = wc * 32 + nj2 * 16 + (mat >> 1) * 8 + l8;
                const uint32_t bd = bbase + 2 * MG_TILE + n * MG_ROWB + kk * 32 + (mat & 1) * 16;
                ldmx4(Bhf[nj2], bd);
                ldmx4(Blf[nj2], bd + MG_TILE);
            }
            #pragma unroll
            for (int mi = 0; mi < 4; mi++)
                #pragma unroll
                for (int nj = 0; nj < 4; nj++) {
                    const int g = nj >> 1, o = (nj & 1) * 2;
                    mma16816(d[mi][nj], Ah[mi], Bhf[g][o], Bhf[g][o + 1]);
                    mma16816(d[mi][nj], Ah[mi], Blf[g][o], Blf[g][o + 1]);
                    mma16816(d[mi][nj], Al[mi], Bhf[g][o], Bhf[g][o + 1]);
                }
        }
        __syncthreads();
    }

    #pragma unroll
    for (int mi = 0; mi < 4; mi++) {
        #pragma unroll
        for (int nj = 0; nj < 4; nj++) {
            const int row = m0 + wr * 64 + mi * 16 + (lane >> 2);
            const int col = n0 + wc * 32 + nj * 8 + (lane & 3) * 2;
            #pragma unroll
            for (int hh = 0; hh < 2; hh++) {
                const int m = row + hh * 8;
                float2 cv = make_float2(d[mi][nj][hh * 2], d[mi][nj][hh * 2 + 1]);
                if constexpr (EPI == 1) {
                    const float2 rv = *reinterpret_cast<const float2*>(
                        E + (size_t)m * ldc + col);
                    cv.x += rv.x; cv.y += rv.y;
                }
                *reinterpret_cast<float2*>(C + (size_t)m * ldc + col) = cv;
            }
        }
    }
}

// QKV GEMM: all three outputs split bf16 (q, k, v same [row,512] layout).
__global__ __launch_bounds__(256) void mgemm_qkv_k(
    const __nv_bfloat16* __restrict__ ah, const __nv_bfloat16* __restrict__ al,
    const __nv_bfloat16* __restrict__ wh, const __nv_bfloat16* __restrict__ wl,
    __nv_bfloat16* __restrict__ qh, __nv_bfloat16* __restrict__ ql,
    __nv_bfloat16* __restrict__ kh, __nv_bfloat16* __restrict__ kl,
    __nv_bfloat16* __restrict__ vh, __nv_bfloat16* __restrict__ vl,
    size_t wSlot)
{
    constexpr int K = DMODEL;
    extern __shared__ char smem[];
    const uint32_t sb = smem_u32(smem);
    const int t = threadIdx.x;
    const int lane = t & 31, wid = t >> 5;
    const int wr = wid & 1, wc = wid >> 1;
    const int z = blockIdx.z;
    const __nv_bfloat16* Bh = wh + (size_t)z * wSlot;
    const __nv_bfloat16* Bl = wl + (size_t)z * wSlot;
    const int m0 = blockIdx.y * 128, n0 = blockIdx.x * 128;

    float d[4][4][4];
    #pragma unroll
    for (int mi = 0; mi < 4; mi++)
        #pragma unroll
        for (int nj = 0; nj < 4; nj++)
            #pragma unroll
            for (int r = 0; r < 4; r++) d[mi][nj][r] = 0.f;

    const int lr = t >> 2;
    const int lc = t & 3;
    const __nv_bfloat16* srcs[4] = { ah, al, Bh, Bl };

    auto issue = [&](int kc, int buf) {
        const uint32_t base = sb + buf * MG_BUF;
        #pragma unroll
        for (int tile = 0; tile < 4; tile++) {
            const __nv_bfloat16* s = srcs[tile];
            const int baseRow = (tile < 2) ? m0 : n0;
            #pragma unroll
            for (int h = 0; h < 2; h++) {
                const int row = lr + h * 64;
                const __nv_bfloat16* g = s + (size_t)(baseRow + row) * K + kc * 32 + lc * 8;
                CP_ASYNC16(base + tile * MG_TILE + row * MG_ROWB + lc * 16, g);
            }
        }
        CP_COMMIT();
    };

    const int nch = K >> 5;
    issue(0, 0);

    const int mat = lane >> 3, l8 = lane & 7;
    for (int kc = 0; kc < nch; kc++) {
        const int buf = kc & 1;
        if (kc + 1 < nch) { issue(kc + 1, buf ^ 1); cp_wait<1>(); }
        else              { cp_wait<0>(); }
        __syncthreads();
        const uint32_t bbase = sb + buf * MG_BUF;
        #pragma unroll
        for (int kk = 0; kk < 2; kk++) {
            uint32_t Ah[4][4], Al[4][4], Bhf[2][4], Blf[2][4];
            #pragma unroll
            for (int mi = 0; mi < 4; mi++) {
                const int row = wr * 64 + mi * 16 + (mat & 1) * 8 + l8;
                const uint32_t ad = bbase + row * MG_ROWB + kk * 32 + (mat >> 1) * 16;
                ldmx4(Ah[mi], ad);
                ldmx4(Al[mi], ad + MG_TILE);
            }
            #pragma unroll
            for (int nj2 = 0; nj2 < 2; nj2++) {
                const int n = wc * 32 + nj2 * 16 + (mat >> 1) * 8 + l8;
                const uint32_t bd = bbase + 2 * MG_TILE + n * MG_ROWB + kk * 32 + (mat & 1) * 16;
                ldmx4(Bhf[nj2], bd);
                ldmx4(Blf[nj2], bd + MG_TILE);
            }
            #pragma unroll
            for (int mi = 0; mi < 4; mi++)
                #pragma unroll
                for (int nj = 0; nj < 4; nj++) {
                    const int g = nj >> 1, o = (nj & 1) * 2;
                    mma16816(d[mi][nj], Ah[mi], Bhf[g][o], Bhf[g][o + 1]);
                    mma16816(d[mi][nj], Ah[mi], Blf[g][o], Blf[g][o + 1]);
                    mma16816(d[mi][nj], Al[mi], Bhf[g][o], Bhf[g][o + 1]);
                }
        }
        __syncthreads();
    }

    __nv_bfloat16* H = (z == 0) ? qh : (z == 1) ? kh : vh;
    __nv_bfloat16* L = (z == 0) ? ql : (z == 1) ? kl : vl;
    #pragma unroll
    for (int mi = 0; mi < 4; mi++) {
        #pragma unroll
        for (int nj = 0; nj < 4; nj++) {
            const int row = m0 + wr * 64 + mi * 16 + (lane >> 2);
            const int col = n0 + wc * 32 + nj * 8 + (lane & 3) * 2;
            #pragma unroll
            for (int hh = 0; hh < 2; hh++) {
                const int m = row + hh * 8;
                const size_t off = (size_t)m * DMODEL + col;
                split_store2(d[mi][nj][hh * 2], d[mi][nj][hh * 2 + 1],
                             H + off, L + off);
            }
        }
    }
}

// FFN-in fused: gelu(A@W0) * (A@W1), split bf16 out.
#define FFN_BUF  (6 * MG_TILE)
#define FFN_SMEM (2 * FFN_BUF)
__global__ __launch_bounds__(256) void mgemm_ffn_k(
    const __nv_bfloat16* __restrict__ ah, const __nv_bfloat16* __restrict__ al,
    const __nv_bfloat16* __restrict__ w0h, const __nv_bfloat16* __restrict__ w0l,
    const __nv_bfloat16* __restrict__ w1h, const __nv_bfloat16* __restrict__ w1l,
    __nv_bfloat16* __restrict__ Ghi, __nv_bfloat16* __restrict__ Glo)
{
    constexpr int K = DMODEL;
    extern __shared__ char smem[];
    const uint32_t sb = smem_u32(smem);
    const int t = threadIdx.x;
    const int lane = t & 31, wid = t >> 5;
    const int wr = wid & 1, wc = wid >> 1;
    const int m0 = blockIdx.y * 128, n0 = blockIdx.x * 128;

    float d0[4][4][4], d1[4][4][4];
    #pragma unroll
    for (int mi = 0; mi < 4; mi++)
        #pragma unroll
        for (int nj = 0; nj < 4; nj++)
            #pragma unroll
            for (int r = 0; r < 4; r++) { d0[mi][nj][r] = 0.f; d1[mi][nj][r] = 0.f; }

    const int lr = t >> 2;
    const int lc = t & 3;
    const __nv_bfloat16* srcs[6] = { ah, al, w0h, w0l, w1h, w1l };

    auto issue = [&](int kc, int buf) {
        const uint32_t base = sb + buf * FFN_BUF;
        #pragma unroll
        for (int tile = 0; tile < 6; tile++) {
            const __nv_bfloat16* s = srcs[tile];
            const int baseRow = (tile < 2) ? m0 : n0;
            #pragma unroll
            for (int h = 0; h < 2; h++) {
                const int row = lr + h * 64;
                const __nv_bfloat16* g = s + (size_t)(baseRow + row) * K + kc * 32 + lc * 8;
                CP_ASYNC16(base + tile * MG_TILE + row * MG_ROWB + lc * 16, g);
            }
        }
        CP_COMMIT();
    };

    const int nch = K >> 5;
    issue(0, 0);

    const int mat = lane >> 3, l8 = lane & 7;
    for (int kc = 0; kc < nch; kc++) {
        const int buf = kc & 1;
        if (kc + 1 < nch) { issue(kc + 1, buf ^ 1); cp_wait<1>(); }
        else              { cp_wait<0>(); }
        __syncthreads();
        const uint32_t bbase = sb + buf * FFN_BUF;
        #pragma unroll
        for (int kk = 0; kk < 2; kk++) {
            uint32_t Ah[4][4], Al[4][4];
            #pragma unroll
            for (int mi = 0; mi < 4; mi++) {
                const int row = wr * 64 + mi * 16 + (mat & 1) * 8 + l8;
                const uint32_t ad = bbase + row * MG_ROWB + kk * 32 + (mat >> 1) * 16;
                ldmx4(Ah[mi], ad);
                ldmx4(Al[mi], ad + MG_TILE);
            }
            #pragma unroll
            for (int w = 0; w < 2; w++) {
                uint32_t Bhf[2][4], Blf[2][4];
                const uint32_t boff = bbase + (2 + 2 * w) * MG_TILE;
                #pragma unroll
                for (int nj2 = 0; nj2 < 2; nj2++) {
                    const int n = wc * 32 + nj2 * 16 + (mat >> 1) * 8 + l8;
                    const uint32_t bd = boff + n * MG_ROWB + kk * 32 + (mat & 1) * 16;
                    ldmx4(Bhf[nj2], bd);
                    ldmx4(Blf[nj2], bd + MG_TILE);
                }
                #pragma unroll
                for (int mi = 0; mi < 4; mi++)
                    #pragma unroll
                    for (int nj = 0; nj < 4; nj++) {
                        float* dd = w ? d1[mi][nj] : d0[mi][nj];
                        const int g = nj >> 1, o = (nj & 1) * 2;
                        mma16816(dd, Ah[mi], Bhf[g][o], Bhf[g][o + 1]);
                        mma16816(dd, Ah[mi], Blf[g][o], Blf[g][o + 1]);
                        mma16816(dd, Al[mi], Bhf[g][o], Bhf[g][o + 1]);
                    }
            }
        }
        __syncthreads();
    }

    #pragma unroll
    for (int mi = 0; mi < 4; mi++) {
        #pragma unroll
        for (int nj = 0; nj < 4; nj++) {
            const int row = m0 + wr * 64 + mi * 16 + (lane >> 2);
            const int col = n0 + wc * 32 + nj * 8 + (lane & 3) * 2;
            #pragma unroll
            for (int hh = 0; hh < 2; hh++) {
                const int m = row + hh * 8;
                const size_t off = (size_t)m * DFF_ + col;
                float r0 = gelu_new(d0[mi][nj][hh * 2])     * d1[mi][nj][hh * 2];
                float r1 = gelu_new(d0[mi][nj][hh * 2 + 1]) * d1[mi][nj][hh * 2 + 1];
                split_store2(r0, r1, Ghi + off, Glo + off);
            }
        }
    }
}

// ---------------- fused flash attention (smem bias table, row-major V + ldmatrix.trans) ----------------
#define FL_QSTR 144
#define FL_QT   (128 * FL_QSTR)
#define FL_OFF_K(buf) (2 * FL_QT + (buf) * 2 * FL_QT)
#define FL_OFF_V(buf) (6 * FL_QT + (buf) * 2 * FL_QT)
#define FL_BIAS_OFF (10 * FL_QT)          // 184320
#define FL_SMEM (FL_BIAS_OFF + 16384)     // 200704
__global__ __launch_bounds__(256) void flash_k(
    const __nv_bfloat16* __restrict__ qh_g, const __nv_bfloat16* __restrict__ ql_g,
    const __nv_bfloat16* __restrict__ kh_g, const __nv_bfloat16* __restrict__ kl_g,
    const __nv_bfloat16* __restrict__ vh_g, const __nv_bfloat16* __restrict__ vl_g,
    const float* __restrict__ btab,
    __nv_bfloat16* __restrict__ Ohi, __nv_bfloat16* __restrict__ Olo)
{
    extern __shared__ char smem[];
    const uint32_t sb = smem_u32(smem);
    float* smb = reinterpret_cast<float*>(smem + FL_BIAS_OFF);
    const int t = threadIdx.x, lane = t & 31, wid = t >> 5;
    const int z = blockIdx.z, zb = z >> 3, zh = z & 7;
    const int m0 = blockIdx.x * 128;
    const int mat = lane >> 3, l8 = lane & 7;

    auto loadQ = [&]() {
        #pragma unroll
        for (int i = 0; i < 4; i++) {
            int idx = t + i * 256, row = idx >> 3, c = idx & 7;
            size_t go = (size_t)(zb * SEQ + m0 + row) * DMODEL + zh * 64 + c * 8;
            CP_ASYNC16(sb + row * FL_QSTR + c * 16, qh_g + go);
            CP_ASYNC16(sb + FL_QT + row * FL_QSTR + c * 16, ql_g + go);
        }
    };
    auto loadKV = [&](int kt, int buf) {
        #pragma unroll
        for (int i = 0; i < 4; i++) {
            int idx = t + i * 256, row = idx >> 3, c = idx & 7;
            size_t go = (size_t)(zb * SEQ + kt * 128 + row) * DMODEL + zh * 64 + c * 8;
            CP_ASYNC16(sb + FL_OFF_K(buf) + row * FL_QSTR + c * 16, kh_g + go);
            CP_ASYNC16(sb + FL_OFF_K(buf) + FL_QT + row * FL_QSTR + c * 16, kl_g + go);
            CP_ASYNC16(sb + FL_OFF_V(buf) + row * FL_QSTR + c * 16, vh_g + go);
            CP_ASYNC16(sb + FL_OFF_V(buf) + FL_QT + row * FL_QSTR + c * 16, vl_g + go);
        }
        CP_COMMIT();
    };

    loadQ();
    loadKV(0, 0);
    for (int i = t; i < NRELS; i += 256) smb[i] = btab[zh * NRELS + i];

    float m_[2] = { -1e30f, -1e30f }, l_[2] = { 0.f, 0.f };
    float o[8][4];
    #pragma unroll
    for (int nt = 0; nt < 8; nt++)
        #pragma unroll
        for (int e = 0; e < 4; e++) o[nt][e] = 0.f;
    uint32_t qh[4][4], ql[4][4];

    for (int kt = 0; kt < 16; kt++) {
        const int buf = kt & 1;
        if (kt + 1 < 16) { loadKV(kt + 1, buf ^ 1); cp_wait<1>(); }
        else             { cp_wait<0>(); }
        __syncthreads();
        if (kt == 0) {
            #pragma unroll
            for (int kc = 0; kc < 4; kc++) {
                const int row = wid * 16 + (mat & 1) * 8 + l8;
                const uint32_t ad = sb + row * FL_QSTR + kc * 32 + (mat >> 1) * 16;
                ldmx4(qh[kc], ad);
                ldmx4(ql[kc], ad + FL_QT);
            }
        }
        float s[16][4];
        #pragma unroll
        for (int j = 0; j < 16; j++)
            #pragma unroll
            for (int e = 0; e < 4; e++) s[j][e] = 0.f;
        #pragma unroll
        for (int j2 = 0; j2 < 8; j2++) {
            const int n = j2 * 16 + (mat >> 1) * 8 + l8;
            #pragma unroll
            for (int kc = 0; kc < 4; kc++) {
                uint32_t bh4[4], bl4[4];
                const uint32_t bd = sb + FL_OFF_K(buf) + n * FL_QSTR + kc * 32 + (mat & 1) * 16;
                ldmx4(bh4, bd);
                ldmx4(bl4, bd + FL_QT);
                #pragma unroll
                for (int e = 0; e < 2; e++) {
                    mma16816(s[j2 * 2 + e], qh[kc], bh4[e * 2], bh4[e * 2 + 1]);
                    mma16816(s[j2 * 2 + e], qh[kc], bl4[e * 2], bl4[e * 2 + 1]);
                    mma16816(s[j2 * 2 + e], ql[kc], bh4[e * 2], bh4[e * 2 + 1]);
                }
            }
        }
        const int r0 = m0 + wid * 16 + (lane >> 2);
        const int relbase = kt * 128 + 2 * (lane & 3) - r0 + 2047;
        #pragma unroll
        for (int j = 0; j < 16; j++) {
            const int idx = relbase + j * 8;
            s[j][0] += smb[idx];     s[j][1] += smb[idx + 1];
            s[j][2] += smb[idx - 8]; s[j][3] += smb[idx - 7];
        }
        float mx[2] = { -1e30f, -1e30f };
        #pragma unroll
        for (int j = 0; j < 16; j++) {
            mx[0] = fmaxf(mx[0], fmaxf(s[j][0], s[j][1]));
            mx[1] = fmaxf(mx[1], fmaxf(s[j][2], s[j][3]));
        }
        #pragma unroll
        for (int off = 1; off <= 2; off <<= 1) {
            mx[0] = fmaxf(mx[0], __shfl_xor_sync(0xffffffffu, mx[0], off));
            mx[1] = fmaxf(mx[1], __shfl_xor_sync(0xffffffffu, mx[1], off));
        }
        float al2[2];
        #pragma unroll
        for (int h = 0; h < 2; h++) {
            const float nm = fmaxf(m_[h], mx[h]);
            al2[h] = __expf(m_[h] - nm);
            m_[h] = nm;
        }
        float rs[2] = { 0.f, 0.f };
        #pragma unroll
        for (int j = 0; j < 16; j++) {
            s[j][0] = __expf(s[j][0] - m_[0]);
            s[j][1] = __expf(s[j][1] - m_[0]);
            s[j][2] = __expf(s[j][2] - m_[1]);
            s[j][3] = __expf(s[j][3] - m_[1]);
            rs[0] += s[j][0] + s[j][1];
            rs[1] += s[j][2] + s[j][3];
        }
        #pragma unroll
        for (int off = 1; off <= 2; off <<= 1) {
            rs[0] += __shfl_xor_sync(0xffffffffu, rs[0], off);
            rs[1] += __shfl_xor_sync(0xffffffffu, rs[1], off);
        }
        l_[0] = l_[0] * al2[0] + rs[0];
        l_[1] = l_[1] * al2[1] + rs[1];
        #pragma unroll
        for (int nt = 0; nt < 8; nt++) {
            o[nt][0] *= al2[0]; o[nt][1] *= al2[0];
            o[nt][2] *= al2[1]; o[nt][3] *= al2[1];
        }
        #pragma unroll
        for (int kc2 = 0; kc2 < 8; kc2++) {
            uint32_t pa[4], pl[4];
            #pragma unroll
            for (int u = 0; u < 2; u++) {
                #pragma unroll
                for (int hh = 0; hh < 2; hh++) {
                    const float v0 = s[2 * kc2 + u][hh * 2];
                    const float v1 = s[2 * kc2 + u][hh * 2 + 1];
                    __nv_bfloat16 h0, h1, lo0, lo1;
                    split_bf16(v0, h0, lo0);
                    split_bf16(v1, h1, lo1);
                    pa[u * 2 + hh] = pack_bf(h0, h1);
                    pl[u * 2 + hh] = pack_bf(lo0, lo1);
                }
            }
            #pragma unroll
            for (int j2v = 0; j2v < 4; j2v++) {
                uint32_t vh4[4], vl4[4];
                const uint32_t bd = sb + FL_OFF_V(buf)
                    + (kc2 * 16 + (mat & 1) * 8 + l8) * FL_QSTR
                    + (j2v * 16 + (mat >> 1) * 8) * 2;
                ldmx4t(vh4, bd);
                ldmx4t(vl4, bd + FL_QT);
                #pragma unroll
                for (int e = 0; e < 2; e++) {
                    const int nt = j2v * 2 + e;
                    mma16816(o[nt], pa, vh4[e * 2], vh4[e * 2 + 1]);
                    mma16816(o[nt], pa, vl4[e * 2], vl4[e * 2 + 1]);
                    mma16816(o[nt], pl, vh4[e * 2], vh4[e * 2 + 1]);
                }
            }
        }
        __syncthreads();
    }

    const float inv0 = 1.0f / l_[0], inv1 = 1.0f / l_[1];
    const int r0 = m0 + wid * 16 + (lane >> 2);
    #pragma unroll
    for (int nt = 0; nt < 8; nt++) {
        const int col = zh * 64 + nt * 8 + 2 * (lane & 3);
        const size_t o0 = (size_t)(zb * SEQ + r0) * DMODEL + col;
        const size_t o1 = (size_t)(zb * SEQ + r0 + 8) * DMODEL + col;
        split_store2(o[nt][0] * inv0, o[nt][1] * inv0, Ohi + o0, Olo + o0);
        split_store2(o[nt][2] * inv1, o[nt][3] * inv1, Ohi + o1, Olo + o1);
    }
}

// ---------------- launch ----------------
extern "C" void kernel_launch(void* const* d_in, const int* in_sizes, int n_in,
                              void* d_out, int out_size) {
    const int*   ids    = (const int*)  d_in[0];
    const float* embed  = (const float*)d_in[1];
    const float* Wq     = (const float*)d_in[2];
    const float* Wk     = (const float*)d_in[3];
    const float* Wv     = (const float*)d_in[4];
    const float* Wo     = (const float*)d_in[5];
    const float* relb   = (const float*)d_in[6];
    const float* wi0    = (const float*)d_in[7];
    const float* wi1    = (const float*)d_in[8];
    const float* wo_ffn = (const float*)d_in[9];
    const float* ln0    = (const float*)d_in[10];
    const float* ln1    = (const float*)d_in[11];
    const float* flw    = (const float*)d_in[12];
    float* out = (float*)d_out;

    float *x, *f0, *f1, *btab;
    __nv_bfloat16 *ah, *al, *oh, *ol, *vh, *vl, *wh, *wl;
    cudaGetSymbolAddress((void**)&x,  g_x);
    cudaGetSymbolAddress((void**)&f0, g_f0);
    cudaGetSymbolAddress((void**)&f1, g_f1);
    cudaGetSymbolAddress((void**)&btab, g_btab);
    cudaGetSymbolAddress((void**)&ah, g_ah);
    cudaGetSymbolAddress((void**)&al, g_al);
    cudaGetSymbolAddress((void**)&oh, g_oh);
    cudaGetSymbolAddress((void**)&ol, g_ol);
    cudaGetSymbolAddress((void**)&vh, g_vh);
    cudaGetSymbolAddress((void**)&vl, g_vl);
    cudaGetSymbolAddress((void**)&wh, g_wh);
    cudaGetSymbolAddress((void**)&wl, g_wl);
    __nv_bfloat16* gh = (__nv_bfloat16*)f0;
    __nv_bfloat16* gl = (__nv_bfloat16*)f1;

    cudaFuncSetAttribute(mgemm_k<0>, cudaFuncAttributeMaxDynamicSharedMemorySize, MG_SMEM);
    cudaFuncSetAttribute(mgemm_k<1>, cudaFuncAttributeMaxDynamicSharedMemorySize, MG_SMEM);
    cudaFuncSetAttribute(mgemm_qkv_k, cudaFuncAttributeMaxDynamicSharedMemorySize, MG_SMEM);
    cudaFuncSetAttribute(mgemm_ffn_k, cudaFuncAttributeMaxDynamicSharedMemorySize, FFN_SMEM);
    cudaFuncSetAttribute(flash_k, cudaFuncAttributeMaxDynamicSharedMemorySize, FL_SMEM);

    float* out_bias = ((size_t)out_size > OUTX) ? (out + OUTX) : nullptr;

    embed_k<<<NROWS, 256>>>(ids, embed, x);
    bias_tab_k<<<(NH * NRELS + 255) / 256, 256>>>(relb, btab);
    if (out_bias) {
        size_t nb = ((size_t)NH * SEQ * SEQ + 255) / 256;
        bias_out_k<<<(unsigned)nb, 256>>>(btab, out_bias);
    }
    // ---- hoisted all-layer weight conversions (3 merged launches) ----
    {
        // Wq/Wk/Wv/Wo -> arena slots [0,16)*DDc
        cvt_wt_multi_k<<<dim3(16, 16, 16), 256>>>(Wq, Wk, Wv, Wo,
                                                  wh, wl, DMODEL, DMODEL);
        // wi0/wi1 -> arena 16*DDc + [0,8)*DFc
        cvt_wt_multi_k<<<dim3(32, 16, 8), 256>>>(wi0, wi1, wi0, wi1,
                                                 wh + 16 * DDc, wl + 16 * DDc,
                                                 DMODEL, DFF_);
        // wo_ffn (K=DFF, N=DMODEL) -> arena 16*DDc + 8*DFc + [0,4)*DFc
        cvt_wt_multi_k<<<dim3(16, 32, 4), 256>>>(wo_ffn, wo_ffn, wo_ffn, wo_ffn,
                                                 wh + 16 * DDc + 8 * DFc,
                                                 wl + 16 * DDc + 8 * DFc,
                                                 DFF_, DMODEL);
    }

    for (int i = 0; i < NL; i++) {
        const size_t wQKV = (size_t)i * DDc;
        const size_t wO   = 12 * DDc + (size_t)i * DDc;
        const size_t wI0  = 16 * DDc + (size_t)i * DFc;
        const size_t wI1  = 16 * DDc + 4 * DFc + (size_t)i * DFc;
        const size_t wOF  = 16 * DDc + 8 * DFc + (size_t)i * DFc;
        // ---- self attention ----
        rms_split_k<<<NROWS, 256>>>(x, ln0 + (size_t)i * DMODEL, ah, al);
        mgemm_qkv_k<<<dim3(4, 32, 3), 256, MG_SMEM>>>(ah, al, wh + wQKV, wl + wQKV,
                                                      oh, ol,
                                                      ah + QKSZ, al + QKSZ,
                                                      vh, vl, 4 * DDc);
        flash_k<<<dim3(SEQ / 128, 1, BATCH * NH), 256, FL_SMEM>>>(
            oh, ol, ah + QKSZ, al + QKSZ, vh, vl, btab, ah, al);
        mgemm_k<1><<<dim3(4, 32, 1), 256, MG_SMEM>>>(ah, al, wh + wO, wl + wO,
                                                     x, x, x, x,
                                                     DMODEL, DMODEL, 0);
        // ---- gated-GELU FFN (fused) ----
        rms_split_k<<<NROWS, 256>>>(x, ln1 + (size_t)i * DMODEL, ah, al);
        mgemm_ffn_k<<<dim3(DFF_ / 128, NROWS / 128), 256, FFN_SMEM>>>(
            ah, al, wh + wI0, wl + wI0, wh + wI1, wl + wI1, gh, gl);
        mgemm_k<1><<<dim3(4, 32, 1), 256, MG_SMEM>>>(gh, gl, wh + wOF, wl + wOF,
                                                     x, x, x, x,
                                                     DFF_, DMODEL, 0);
    }
    rms_k<<<NROWS, 256>>>(x, flw, out);
}